// round 2
// baseline (speedup 1.0000x reference)
#include <cuda_runtime.h>

// Problem constants
#define IMG_H 512
#define IMG_W 512
#define NIMG  64
#define NPIX  (NIMG * IMG_H * IMG_W)   // 16,777,216

#define TILE     64
#define HALO     5
#define SW       74          // TILE + 2*HALO
#define XS_STRIDE 76         // padded row stride (float4-aligned)
#define NTHREADS 512
#define NBLOCKS  4096        // 64 images * 8 * 8 tiles

// SMEM (floats): xs,ys: 2*74*76 = 11248 ; mid4: 74*64*4 = 18944 ; mid1: 4736
#define SMEM_FLOATS (2 * SW * XS_STRIDE + 5 * SW * TILE)
#define SMEM_BYTES  (SMEM_FLOATS * 4)    // 139,712 bytes

// Separable Gaussian (sigma=1.5, 11 taps), normalized — compile-time literals so
// ptxas emits FFMA R,R,IMM,R (rt_SMSP=1, 2x throughput vs 3-reg form).
__device__ __constant__ const float kDummy = 0.f; // keep TU non-empty of constants
#define W0 0.00102838f
#define W1 0.00759876f
#define W2 0.03600077f
#define W3 0.10936060f
#define W4 0.21300553f
#define W5 0.26601172f
__device__ constexpr float GW[11] = {W0, W1, W2, W3, W4, W5, W4, W3, W2, W1, W0};

__device__ float g_partials[NBLOCKS];
__device__ int   g_count = 0;

extern __shared__ float smem[];

__global__ __launch_bounds__(NTHREADS, 1)
void ssim_fused_kernel(const float* __restrict__ img1, const float* __restrict__ img2,
                       float* __restrict__ out) {
    float*  xs   = smem;
    float*  ys   = xs + SW * XS_STRIDE;
    float4* mid4 = (float4*)(ys + SW * XS_STRIDE);   // (sx, sy, sxx, syy)
    float*  mid1 = (float*)(mid4 + SW * TILE);       // sxy

    const int tid = threadIdx.x;
    const int img = blockIdx.z;
    const int r0  = blockIdx.y * TILE;
    const int c0  = blockIdx.x * TILE;
    const float* p1 = img1 + (size_t)img * (IMG_H * IMG_W);
    const float* p2 = img2 + (size_t)img * (IMG_H * IMG_W);

    // ---- Load halo tile (zero padding outside image) ----
    for (int idx = tid; idx < SW * SW; idx += NTHREADS) {
        int r = idx / SW;
        int c = idx - r * SW;
        int gr = r0 + r - HALO;
        int gc = c0 + c - HALO;
        float a = 0.f, b = 0.f;
        if (gr >= 0 && gr < IMG_H && gc >= 0 && gc < IMG_W) {
            int o = gr * IMG_W + gc;
            a = p1[o];
            b = p2[o];
        }
        xs[r * XS_STRIDE + c] = a;
        ys[r * XS_STRIDE + c] = b;
    }
    __syncthreads();

    // ---- Horizontal pass: per unit = (row, 4 output cols). All taps FFMA-imm. ----
    for (int unit = tid; unit < SW * (TILE / 4); unit += NTHREADS) {
        int row = unit >> 4;
        int cb  = (unit & 15) * 4;

        float xv[16], yv[16];
        const float4* xr4 = (const float4*)(xs + row * XS_STRIDE + cb);
        const float4* yr4 = (const float4*)(ys + row * XS_STRIDE + cb);
        #pragma unroll
        for (int i = 0; i < 4; i++) {
            float4 vx = xr4[i];
            float4 vy = yr4[i];
            xv[i*4+0] = vx.x; xv[i*4+1] = vx.y; xv[i*4+2] = vx.z; xv[i*4+3] = vx.w;
            yv[i*4+0] = vy.x; yv[i*4+1] = vy.y; yv[i*4+2] = vy.z; yv[i*4+3] = vy.w;
        }

        float p[14];
        float sxy[4], sx[4], sy[4], sxx[4], syy[4];

        // sxy from x*y products
        #pragma unroll
        for (int i = 0; i < 14; i++) p[i] = xv[i] * yv[i];
        #pragma unroll
        for (int j = 0; j < 4; j++) {
            float a = 0.f;
            #pragma unroll
            for (int t = 0; t < 11; t++) a = fmaf(GW[t], p[j + t], a);
            sxy[j] = a;
        }
        // sx, sxx from x
        #pragma unroll
        for (int j = 0; j < 4; j++) {
            float a = 0.f;
            #pragma unroll
            for (int t = 0; t < 11; t++) a = fmaf(GW[t], xv[j + t], a);
            sx[j] = a;
        }
        #pragma unroll
        for (int i = 0; i < 14; i++) p[i] = xv[i] * xv[i];
        #pragma unroll
        for (int j = 0; j < 4; j++) {
            float a = 0.f;
            #pragma unroll
            for (int t = 0; t < 11; t++) a = fmaf(GW[t], p[j + t], a);
            sxx[j] = a;
        }
        // sy, syy from y
        #pragma unroll
        for (int j = 0; j < 4; j++) {
            float a = 0.f;
            #pragma unroll
            for (int t = 0; t < 11; t++) a = fmaf(GW[t], yv[j + t], a);
            sy[j] = a;
        }
        #pragma unroll
        for (int i = 0; i < 14; i++) p[i] = yv[i] * yv[i];
        #pragma unroll
        for (int j = 0; j < 4; j++) {
            float a = 0.f;
            #pragma unroll
            for (int t = 0; t < 11; t++) a = fmaf(GW[t], p[j + t], a);
            syy[j] = a;
        }

        int o = row * TILE + cb;
        #pragma unroll
        for (int j = 0; j < 4; j++) {
            mid4[o + j] = make_float4(sx[j], sy[j], sxx[j], syy[j]);
            mid1[o + j] = sxy[j];
        }
    }
    __syncthreads();

    // ---- Vertical pass + SSIM map ----
    float local = 0.f;
    const int col   = tid & (TILE - 1);
    const int rbase = (tid >> 6) * 8;

    const float C1 = 0.0001f;
    const float C2 = 0.0009f;

    #pragma unroll
    for (int half = 0; half < 2; half++) {
        int rb = rbase + half * 4;
        float ax[4] = {0,0,0,0};
        float ay[4] = {0,0,0,0};
        float axx[4] = {0,0,0,0};
        float ayy[4] = {0,0,0,0};
        float axy[4] = {0,0,0,0};

        #pragma unroll
        for (int k = 0; k < 14; k++) {
            int o = (rb + k) * TILE + col;
            float4 m = mid4[o];
            float  e = mid1[o];
            #pragma unroll
            for (int j = 0; j < 4; j++) {
                int t = k - j;
                if (t >= 0 && t < 11) {
                    ax[j]  = fmaf(GW[t], m.x, ax[j]);
                    ay[j]  = fmaf(GW[t], m.y, ay[j]);
                    axx[j] = fmaf(GW[t], m.z, axx[j]);
                    ayy[j] = fmaf(GW[t], m.w, ayy[j]);
                    axy[j] = fmaf(GW[t], e,   axy[j]);
                }
            }
        }

        #pragma unroll
        for (int j = 0; j < 4; j++) {
            float mu1  = ax[j];
            float mu2  = ay[j];
            float mu1s = mu1 * mu1;
            float mu2s = mu2 * mu2;
            float mu12 = mu1 * mu2;
            float s1   = axx[j] - mu1s;
            float s2   = ayy[j] - mu2s;
            float s12  = axy[j] - mu12;
            float num  = (2.f * mu12 + C1) * (2.f * s12 + C2);
            float den  = (mu1s + mu2s + C1) * (s1 + s2 + C2);
            local += num / den;
        }
    }

    // ---- Block reduction (fixed order -> deterministic) ----
    #pragma unroll
    for (int off = 16; off > 0; off >>= 1)
        local += __shfl_xor_sync(0xffffffffu, local, off);

    __shared__ float wsum[16];
    __shared__ int   s_last;
    if ((tid & 31) == 0) wsum[tid >> 5] = local;
    __syncthreads();
    if (tid == 0) {
        float s = 0.f;
        #pragma unroll
        for (int w = 0; w < 16; w++) s += wsum[w];
        int bid = (blockIdx.z * gridDim.y + blockIdx.y) * gridDim.x + blockIdx.x;
        g_partials[bid] = s;
        __threadfence();
        int old = atomicAdd(&g_count, 1);
        s_last = (old == NBLOCKS - 1);
    }
    __syncthreads();

    // ---- Last block: deterministic final reduction in fp64, reset counter ----
    if (s_last) {
        __threadfence();  // acquire: make all g_partials visible
        __shared__ double dsh[16];
        double acc = 0.0;
        #pragma unroll
        for (int i = 0; i < NBLOCKS / NTHREADS; i++)
            acc += (double)g_partials[tid * (NBLOCKS / NTHREADS) + i];
        #pragma unroll
        for (int off = 16; off > 0; off >>= 1)
            acc += __shfl_xor_sync(0xffffffffu, acc, off);
        if ((tid & 31) == 0) dsh[tid >> 5] = acc;
        __syncthreads();
        if (tid == 0) {
            double s = 0.0;
            #pragma unroll
            for (int w = 0; w < 16; w++) s += dsh[w];
            out[0] = (float)(1.0 - s * (1.0 / (double)NPIX));
            g_count = 0;   // reset for next graph replay
        }
    }
}

extern "C" void kernel_launch(void* const* d_in, const int* in_sizes, int n_in,
                              void* d_out, int out_size) {
    const float* pred   = (const float*)d_in[0];
    const float* target = (const float*)d_in[1];
    float* out = (float*)d_out;

    cudaFuncSetAttribute(ssim_fused_kernel,
                         cudaFuncAttributeMaxDynamicSharedMemorySize, SMEM_BYTES);

    dim3 grid(IMG_W / TILE, IMG_H / TILE, NIMG);   // (8, 8, 64)
    ssim_fused_kernel<<<grid, NTHREADS, SMEM_BYTES>>>(pred, target, out);
}

// round 3
// speedup vs baseline: 1.3689x; 1.3689x over previous
#include <cuda_runtime.h>

// Problem constants
#define IMG_H 512
#define IMG_W 512
#define NIMG  64
#define NPIX  (NIMG * IMG_H * IMG_W)   // 16,777,216

#define TILE_W   32
#define TILE_H   64
#define HALO     5
#define SW_H     74          // TILE_H + 2*HALO (rows incl halo)
#define SW_W     42          // TILE_W + 2*HALO (cols incl halo)
#define XS_STRIDE 44         // padded row stride (float4-aligned: 176B)
#define NTHREADS 512
#define GRID_X   (IMG_W / TILE_W)   // 16
#define GRID_Y   (IMG_H / TILE_H)   // 8
#define NBLOCKS  (GRID_X * GRID_Y * NIMG)   // 8192

// SMEM (floats): xs,ys: 2*74*44 = 6512 ; mid4: 74*32*4 = 9472 ; mid1: 2368
#define SMEM_FLOATS (2 * SW_H * XS_STRIDE + 5 * SW_H * TILE_W)
#define SMEM_BYTES  (SMEM_FLOATS * 4)    // 73,412 bytes -> 2 CTAs/SM

// Separable Gaussian (sigma=1.5, 11 taps), normalized, compile-time literals
// (FFMA R,R,IMM,R form, rt_SMSP=1).
#define W0 0.00102838f
#define W1 0.00759876f
#define W2 0.03600077f
#define W3 0.10936060f
#define W4 0.21300553f
#define W5 0.26601172f
__device__ constexpr float GW[11] = {W0, W1, W2, W3, W4, W5, W4, W3, W2, W1, W0};

__device__ float g_partials[NBLOCKS];
__device__ int   g_count = 0;

extern __shared__ float smem[];

__global__ __launch_bounds__(NTHREADS, 2)
void ssim_fused_kernel(const float* __restrict__ img1, const float* __restrict__ img2,
                       float* __restrict__ out) {
    float*  xs   = smem;
    float*  ys   = xs + SW_H * XS_STRIDE;
    float4* mid4 = (float4*)(ys + SW_H * XS_STRIDE);   // (sx, sy, sxx, syy)
    float*  mid1 = (float*)(mid4 + SW_H * TILE_W);     // sxy

    const int tid = threadIdx.x;
    const int img = blockIdx.z;
    const int r0  = blockIdx.y * TILE_H;
    const int c0  = blockIdx.x * TILE_W;
    const float* p1 = img1 + (size_t)img * (IMG_H * IMG_W);
    const float* p2 = img2 + (size_t)img * (IMG_H * IMG_W);

    // ---- Load halo tile (zero padding outside image) ----
    for (int idx = tid; idx < SW_H * SW_W; idx += NTHREADS) {
        int r = idx / SW_W;
        int c = idx - r * SW_W;
        int gr = r0 + r - HALO;
        int gc = c0 + c - HALO;
        float a = 0.f, b = 0.f;
        if (gr >= 0 && gr < IMG_H && gc >= 0 && gc < IMG_W) {
            int o = gr * IMG_W + gc;
            a = p1[o];
            b = p2[o];
        }
        xs[r * XS_STRIDE + c] = a;
        ys[r * XS_STRIDE + c] = b;
    }
    __syncthreads();

    // ---- Horizontal pass: unit = (row, 4 output cols); 74*8 = 592 units ----
    // Channel-sequential to keep the live register set under the 64-reg cap.
    for (int unit = tid; unit < SW_H * (TILE_W / 4); unit += NTHREADS) {
        int row = unit >> 3;
        int cb  = (unit & 7) * 4;

        float xv[16], yv[16];
        const float4* xr4 = (const float4*)(xs + row * XS_STRIDE + cb);
        const float4* yr4 = (const float4*)(ys + row * XS_STRIDE + cb);
        #pragma unroll
        for (int i = 0; i < 4; i++) {
            float4 vx = xr4[i];
            float4 vy = yr4[i];
            xv[i*4+0] = vx.x; xv[i*4+1] = vx.y; xv[i*4+2] = vx.z; xv[i*4+3] = vx.w;
            yv[i*4+0] = vy.x; yv[i*4+1] = vy.y; yv[i*4+2] = vy.z; yv[i*4+3] = vy.w;
        }

        const int o = row * TILE_W + cb;
        float p[14];
        float acc[4];

        // sxy
        #pragma unroll
        for (int i = 0; i < 14; i++) p[i] = xv[i] * yv[i];
        #pragma unroll
        for (int j = 0; j < 4; j++) {
            float a = 0.f;
            #pragma unroll
            for (int t = 0; t < 11; t++) a = fmaf(GW[t], p[j + t], a);
            mid1[o + j] = a;
        }
        // sx, sy
        float sx[4], sy[4];
        #pragma unroll
        for (int j = 0; j < 4; j++) {
            float a = 0.f, b = 0.f;
            #pragma unroll
            for (int t = 0; t < 11; t++) {
                a = fmaf(GW[t], xv[j + t], a);
                b = fmaf(GW[t], yv[j + t], b);
            }
            sx[j] = a; sy[j] = b;
        }
        // sxx
        #pragma unroll
        for (int i = 0; i < 14; i++) p[i] = xv[i] * xv[i];
        #pragma unroll
        for (int j = 0; j < 4; j++) {
            float a = 0.f;
            #pragma unroll
            for (int t = 0; t < 11; t++) a = fmaf(GW[t], p[j + t], a);
            acc[j] = a;
        }
        // syy + store float4
        #pragma unroll
        for (int i = 0; i < 14; i++) p[i] = yv[i] * yv[i];
        #pragma unroll
        for (int j = 0; j < 4; j++) {
            float a = 0.f;
            #pragma unroll
            for (int t = 0; t < 11; t++) a = fmaf(GW[t], p[j + t], a);
            mid4[o + j] = make_float4(sx[j], sy[j], acc[j], a);
        }
    }
    __syncthreads();

    // ---- Vertical pass + SSIM map: col = tid&31, 16 row-groups of 4 rows ----
    float local = 0.f;
    const int col = tid & (TILE_W - 1);
    const int rb  = (tid >> 5) * 4;     // output rows rb..rb+3

    const float C1 = 0.0001f;
    const float C2 = 0.0009f;

    {
        float ax[4]  = {0,0,0,0};
        float ay[4]  = {0,0,0,0};
        float axx[4] = {0,0,0,0};
        float ayy[4] = {0,0,0,0};
        float axy[4] = {0,0,0,0};

        #pragma unroll
        for (int k = 0; k < 14; k++) {
            int o = (rb + k) * TILE_W + col;
            float4 m = mid4[o];
            float  e = mid1[o];
            #pragma unroll
            for (int j = 0; j < 4; j++) {
                int t = k - j;
                if (t >= 0 && t < 11) {   // compile-time resolved (k,j unrolled)
                    ax[j]  = fmaf(GW[t], m.x, ax[j]);
                    ay[j]  = fmaf(GW[t], m.y, ay[j]);
                    axx[j] = fmaf(GW[t], m.z, axx[j]);
                    ayy[j] = fmaf(GW[t], m.w, ayy[j]);
                    axy[j] = fmaf(GW[t], e,   axy[j]);
                }
            }
        }

        #pragma unroll
        for (int j = 0; j < 4; j++) {
            float mu1  = ax[j];
            float mu2  = ay[j];
            float mu1s = mu1 * mu1;
            float mu2s = mu2 * mu2;
            float mu12 = mu1 * mu2;
            float s1   = axx[j] - mu1s;
            float s2   = ayy[j] - mu2s;
            float s12  = axy[j] - mu12;
            float num  = (2.f * mu12 + C1) * (2.f * s12 + C2);
            float den  = (mu1s + mu2s + C1) * (s1 + s2 + C2);
            local += __fdividef(num, den);
        }
    }

    // ---- Block reduction (fixed order -> deterministic) ----
    #pragma unroll
    for (int off = 16; off > 0; off >>= 1)
        local += __shfl_xor_sync(0xffffffffu, local, off);

    __shared__ float wsum[16];
    __shared__ int   s_last;
    if ((tid & 31) == 0) wsum[tid >> 5] = local;
    __syncthreads();
    if (tid == 0) {
        float s = 0.f;
        #pragma unroll
        for (int w = 0; w < 16; w++) s += wsum[w];
        int bid = (blockIdx.z * gridDim.y + blockIdx.y) * gridDim.x + blockIdx.x;
        g_partials[bid] = s;
        __threadfence();
        int old = atomicAdd(&g_count, 1);
        s_last = (old == NBLOCKS - 1);
    }
    __syncthreads();

    // ---- Last block: deterministic final reduction in fp64, reset counter ----
    if (s_last) {
        __threadfence();
        __shared__ double dsh[16];
        double acc = 0.0;
        #pragma unroll
        for (int i = 0; i < NBLOCKS / NTHREADS; i++)
            acc += (double)g_partials[tid * (NBLOCKS / NTHREADS) + i];
        #pragma unroll
        for (int off = 16; off > 0; off >>= 1)
            acc += __shfl_xor_sync(0xffffffffu, acc, off);
        if ((tid & 31) == 0) dsh[tid >> 5] = acc;
        __syncthreads();
        if (tid == 0) {
            double s = 0.0;
            #pragma unroll
            for (int w = 0; w < 16; w++) s += dsh[w];
            out[0] = (float)(1.0 - s * (1.0 / (double)NPIX));
            g_count = 0;   // reset for next graph replay
        }
    }
}

extern "C" void kernel_launch(void* const* d_in, const int* in_sizes, int n_in,
                              void* d_out, int out_size) {
    const float* pred   = (const float*)d_in[0];
    const float* target = (const float*)d_in[1];
    float* out = (float*)d_out;

    cudaFuncSetAttribute(ssim_fused_kernel,
                         cudaFuncAttributeMaxDynamicSharedMemorySize, SMEM_BYTES);

    dim3 grid(GRID_X, GRID_Y, NIMG);   // (16, 8, 64)
    ssim_fused_kernel<<<grid, NTHREADS, SMEM_BYTES>>>(pred, target, out);
}